// round 3
// baseline (speedup 1.0000x reference)
#include <cuda_runtime.h>
#include <math.h>

// Problem shape (from reference): B=16, S=2048, D=768
#define MAXB 16
#define MAXS 2048
#define MAXD 768

// Scratch (device globals — no allocation allowed)
__device__ float g_w2[MAXD * 3];      // fused conv*linear weights, layout [i*3+k]
__device__ float g_c;                 // fused bias
__device__ float g_alpha[MAXB * MAXS];
__device__ float g_w[MAXB * MAXS];    // per-t primary weight (a_t, or a1 at fire)
__device__ float g_a2[MAXB * MAXS];   // leftover weight (valid at fire positions)
__device__ int   g_F[MAXB * MAXS];    // fire time indices, per batch
__device__ int   g_n[MAXB];           // number of fires per batch

// ---------------------------------------------------------------------------
// Kernel 1: fuse conv_w (D,D,3) with lin_w (D) -> w2 (D,3); also c scalar.
// ---------------------------------------------------------------------------
__global__ void k_fuse(const float* __restrict__ conv_w,
                       const float* __restrict__ conv_b,
                       const float* __restrict__ lin_w,
                       const float* __restrict__ lin_b, int D) {
    if ((int)blockIdx.x == (int)gridDim.x - 1) {
        // c = sum_o lin_w[o]*conv_b[o] + lin_b[0]
        __shared__ float red[256];
        float p = 0.f;
        for (int o = threadIdx.x; o < D; o += 256) p += lin_w[o] * conv_b[o];
        red[threadIdx.x] = p;
        __syncthreads();
        for (int st = 128; st > 0; st >>= 1) {
            if ((int)threadIdx.x < st) red[threadIdx.x] += red[threadIdx.x + st];
            __syncthreads();
        }
        if (threadIdx.x == 0) g_c = red[0] + lin_b[0];
    } else {
        int p = blockIdx.x * 256 + threadIdx.x;   // p = i*3 + k
        if (p < D * 3) {
            float acc = 0.f;
            const int stride = D * 3;
            for (int o = 0; o < D; o++) acc += lin_w[o] * conv_w[(size_t)o * stride + p];
            g_w2[p] = acc;
        }
    }
}

// ---------------------------------------------------------------------------
// Kernel 2: alphas. One warp per sequence position; 8 warps/block.
// alpha[b,s] = sigmoid(c + sum_{k,i} w2[i,k]*x[b, s+k-1, i]), 0 if s>=len[b].
// ---------------------------------------------------------------------------
__global__ void k_alpha(const float* __restrict__ x,
                        const int* __restrict__ lens,
                        int S, int D) {
    extern __shared__ float sw2[];  // D*3 floats
    for (int i = threadIdx.x; i < D * 3; i += blockDim.x) sw2[i] = g_w2[i];
    __syncthreads();

    const int b = blockIdx.y;
    const int warp = threadIdx.x >> 5, lane = threadIdx.x & 31;
    const int s = blockIdx.x * 8 + warp;
    if (s >= S) return;

    const int len = lens[b];
    float acc = 0.f;
    if (s < len) {
        #pragma unroll
        for (int k = 0; k < 3; k++) {
            int r = s + k - 1;
            if (r < 0 || r >= S) continue;
            const float* row = x + ((size_t)b * S + r) * D;
            for (int i = lane; i < D; i += 32) acc += sw2[i * 3 + k] * row[i];
        }
        #pragma unroll
        for (int o = 16; o > 0; o >>= 1) acc += __shfl_xor_sync(0xffffffffu, acc, o);
        acc = 1.f / (1.f + expf(-(acc + g_c)));  // sigmoid
    }
    if (lane == 0) g_alpha[(size_t)b * S + s] = (s < len) ? acc : 0.f;
}

// ---------------------------------------------------------------------------
// Kernel 3: sequential CIF scalar scan, one block per batch, thread 0 scans.
// Replicates reference op order exactly (no FMA on the aacc chain).
// Invalid steps have alpha==0 exactly => identical to reference's masking.
// ---------------------------------------------------------------------------
__global__ void k_scan(int S) {
    __shared__ float sa[MAXS];
    const int b = blockIdx.x;
    for (int t = threadIdx.x; t < S; t += blockDim.x) sa[t] = g_alpha[(size_t)b * S + t];
    __syncthreads();
    if (threadIdx.x != 0) return;

    const int base = b * S;
    float aacc = 0.f;
    int nf = 0;
    for (int t = 0; t < S; t++) {
        float a  = sa[t];
        float s1 = aacc + a;          // aacc_u
        float a1 = 1.0f - aacc;       // weight to emitted segment on fire
        float a2 = a - a1;            // leftover on fire
        bool fire = (s1 >= 1.0f);
        g_w[base + t]  = fire ? a1 : a;
        g_a2[base + t] = a2;
        if (fire) g_F[base + nf++] = t;
        aacc = fire ? a2 : s1;
    }
    g_n[b] = nf;
}

// ---------------------------------------------------------------------------
// Kernel 4: emit output rows. Block (j, b) handles output row j of batch b.
// Row j < n: weighted sum of h over t in [F[j-1], F[j]]; else zeros.
// Threads = D/4, float4 per thread.
// ---------------------------------------------------------------------------
__global__ void k_emit(const float* __restrict__ x, float* __restrict__ out,
                       int B, int S, int D, long long out_size) {
    const int j = blockIdx.x, b = blockIdx.y;
    const int tid = threadIdx.x;
    const int n = g_n[b];

    float4* orow = (float4*)(out + ((size_t)b * S + j) * D);
    if (j >= n) {
        orow[tid] = make_float4(0.f, 0.f, 0.f, 0.f);
    } else {
        const int base = b * S;
        const int t1 = g_F[base + j];
        const int t0 = (j == 0) ? 0 : g_F[base + j - 1];
        float4 acc = make_float4(0.f, 0.f, 0.f, 0.f);
        for (int t = t0; t <= t1; t++) {
            float wgt = (j > 0 && t == t0) ? g_a2[base + t] : g_w[base + t];
            const float4 h = ((const float4*)(x + ((size_t)b * S + t) * D))[tid];
            acc.x += wgt * h.x; acc.y += wgt * h.y;
            acc.z += wgt * h.z; acc.w += wgt * h.w;
        }
        orow[tid] = acc;
    }
    // len_tensor appended after output_c (as output dtype), if space exists
    if (j == 0 && tid == 0 && out_size >= (long long)B * S * D + B)
        out[(size_t)B * S * D + b] = (float)n;
}

// ---------------------------------------------------------------------------
extern "C" void kernel_launch(void* const* d_in, const int* in_sizes, int n_in,
                              void* d_out, int out_size) {
    const float* x      = (const float*)d_in[0];  // encoder_outputs (B,S,D)
    const int*   lens   = (const int*)  d_in[1];  // encoder_lens (B,)
    const float* conv_w = (const float*)d_in[2];  // (D,D,3)
    const float* conv_b = (const float*)d_in[3];  // (D,)
    const float* lin_w  = (const float*)d_in[4];  // (1,D)
    const float* lin_b  = (const float*)d_in[5];  // (1,)

    const int B = in_sizes[1];
    const int D = in_sizes[4];
    const int S = in_sizes[0] / (B * D);
    float* out = (float*)d_out;

    // 1) fuse weights: D*3 values + one c-reduction block
    {
        int nb = (D * 3 + 255) / 256 + 1;
        k_fuse<<<nb, 256>>>(conv_w, conv_b, lin_w, lin_b, D);
    }
    // 2) alphas: warp per position
    {
        dim3 grid((S + 7) / 8, B);
        k_alpha<<<grid, 256, D * 3 * sizeof(float)>>>(x, lens, S, D);
    }
    // 3) sequential scan per batch
    k_scan<<<B, 256>>>(S);
    // 4) emit output rows + lens
    {
        dim3 grid(S, B);
        k_emit<<<grid, D / 4>>>(x, out, B, S, D, (long long)out_size);
    }
}

// round 5
// speedup vs baseline: 1.6977x; 1.6977x over previous
#include <cuda_runtime.h>
#include <math.h>

// Problem shape: B=16, S=2048, D=768
#define MAXB 16
#define MAXS 2048
#define MAXD 768
#define NCHUNK 16   // o-dim chunks for fuse partials

// Scratch (device globals — no allocation allowed)
__device__ float g_part[NCHUNK * MAXD * 3];  // fuse partials [chunk][p]
__device__ float g_w2[MAXD * 3];             // fused conv*linear weights [i*3+k]
__device__ float g_c;                        // fused bias
__device__ float g_z0[MAXB * MAXS];          // per-row dot with w2[:,k]
__device__ float g_z1[MAXB * MAXS];
__device__ float g_z2[MAXB * MAXS];
__device__ float g_alpha[MAXB * MAXS];
__device__ int   g_Ft[MAXB * MAXS];          // fire time indices (compacted)
__device__ float g_Fa1[MAXB * MAXS];         // a1 at fire j
__device__ float g_Fa2[MAXB * MAXS];         // a2 at fire j
__device__ int   g_n[MAXB];

// ---------------------------------------------------------------------------
// Kernel 1a: partial fuse. grid = (9 p-blocks, NCHUNK o-chunks), 256 thr.
// g_part[ch][p] = sum_{o in chunk} lin_w[o] * conv_w[o*3D + p]
// ---------------------------------------------------------------------------
__global__ void k_fuse_part(const float* __restrict__ conv_w,
                            const float* __restrict__ lin_w, int D) {
    const int p = blockIdx.x * 256 + threadIdx.x;     // p = i*3+k
    const int P = D * 3;
    if (p >= P) return;
    const int ch = blockIdx.y;
    const int csz = D / NCHUNK;
    const int o0 = ch * csz;
    float acc = 0.f;
    #pragma unroll 4
    for (int o = o0; o < o0 + csz; o++)
        acc += lin_w[o] * conv_w[(size_t)o * P + p];
    g_part[ch * P + p] = acc;
}

// ---------------------------------------------------------------------------
// Kernel 1b: combine partials (fixed order) + c scalar. 10 blocks of 256.
// ---------------------------------------------------------------------------
__global__ void k_fuse_comb(const float* __restrict__ conv_b,
                            const float* __restrict__ lin_w,
                            const float* __restrict__ lin_b, int D) {
    const int P = D * 3;
    if ((int)blockIdx.x == (int)gridDim.x - 1) {
        __shared__ float red[256];
        float s = 0.f;
        for (int o = threadIdx.x; o < D; o += 256) s += lin_w[o] * conv_b[o];
        red[threadIdx.x] = s;
        __syncthreads();
        for (int st = 128; st > 0; st >>= 1) {
            if ((int)threadIdx.x < st) red[threadIdx.x] += red[threadIdx.x + st];
            __syncthreads();
        }
        if (threadIdx.x == 0) g_c = red[0] + lin_b[0];
    } else {
        int p = blockIdx.x * 256 + threadIdx.x;
        if (p < P) {
            float acc = 0.f;
            #pragma unroll
            for (int ch = 0; ch < NCHUNK; ch++) acc += g_part[ch * P + p];
            g_w2[p] = acc;
        }
    }
}

// ---------------------------------------------------------------------------
// Kernel 2: z_k[r] = dot(x[r], w2[:,k]) for k=0..2. Warp per row, 8 warps/blk.
// x read exactly once. w2 in smem transposed [k][i] for LDS.128.
// ---------------------------------------------------------------------------
__global__ void k_z(const float* __restrict__ x, int S, int D) {
    __shared__ __align__(16) float sw2[3 * MAXD];
    for (int idx = threadIdx.x; idx < D * 3; idx += blockDim.x) {
        int i = idx / 3, k = idx - i * 3;
        sw2[k * D + i] = g_w2[idx];
    }
    __syncthreads();

    const int b = blockIdx.y;
    const int warp = threadIdx.x >> 5, lane = threadIdx.x & 31;
    const int r = blockIdx.x * 8 + warp;
    if (r >= S) return;

    const float4* xr = (const float4*)(x + ((size_t)b * S + r) * D);
    const float4* w0 = (const float4*)(sw2);
    const float4* w1 = (const float4*)(sw2 + D);
    const float4* w2p = (const float4*)(sw2 + 2 * D);
    float a0 = 0.f, a1 = 0.f, a2 = 0.f;
    const int M = D >> 2;   // float4 count
    for (int m = lane; m < M; m += 32) {
        float4 xv = xr[m];
        float4 u = w0[m];
        a0 += u.x * xv.x + u.y * xv.y + u.z * xv.z + u.w * xv.w;
        float4 v = w1[m];
        a1 += v.x * xv.x + v.y * xv.y + v.z * xv.z + v.w * xv.w;
        float4 w = w2p[m];
        a2 += w.x * xv.x + w.y * xv.y + w.z * xv.z + w.w * xv.w;
    }
    #pragma unroll
    for (int o = 16; o > 0; o >>= 1) {
        a0 += __shfl_xor_sync(0xffffffffu, a0, o);
        a1 += __shfl_xor_sync(0xffffffffu, a1, o);
        a2 += __shfl_xor_sync(0xffffffffu, a2, o);
    }
    if (lane == 0) {
        size_t idx = (size_t)b * S + r;
        g_z0[idx] = a0; g_z1[idx] = a1; g_z2[idx] = a2;
    }
}

// ---------------------------------------------------------------------------
// Kernel 3: alpha[b,s] = sigmoid(c + z0[s-1] + z1[s] + z2[s+1]), 0 if s>=len.
// ---------------------------------------------------------------------------
__global__ void k_comb(const int* __restrict__ lens, int B, int S) {
    int idx = blockIdx.x * 256 + threadIdx.x;
    if (idx >= B * S) return;
    int b = idx / S, t = idx - b * S;
    float a = 0.f;
    if (t < lens[b]) {
        float l = g_c + g_z1[idx];
        if (t > 0)     l += g_z0[idx - 1];
        if (t < S - 1) l += g_z2[idx + 1];
        a = 1.f / (1.f + expf(-l));
    }
    g_alpha[idx] = a;
}

// ---------------------------------------------------------------------------
// Kernel 4: sequential CIF scan; one block/batch; thread 0 runs the chain.
// Records (t, a1, a2) at fire positions into smem, cooperative flush after.
// Op order identical to reference; invalid steps have alpha==0 exactly.
// ---------------------------------------------------------------------------
__global__ void k_scan(int S) {
    __shared__ float sa[MAXS];
    __shared__ int   sFt[MAXS];
    __shared__ float sA1[MAXS];
    __shared__ float sA2[MAXS];
    __shared__ int   s_nf;
    const int b = blockIdx.x;
    const int base = b * S;
    for (int t = threadIdx.x; t < S; t += blockDim.x) sa[t] = g_alpha[base + t];
    __syncthreads();

    if (threadIdx.x == 0) {
        float aacc = 0.f;
        int nf = 0;
        #pragma unroll 4
        for (int t = 0; t < S; t++) {
            float a  = sa[t];
            float s1 = aacc + a;           // aacc_u        (FADD, on chain)
            float a1 = 1.0f - aacc;        // fire weight   (parallel)
            float a2 = a - a1;             // leftover
            bool fire = (s1 >= 1.0f);      // FSETP -> data
            // predicated record, off the aacc chain
            sFt[nf] = t; sA1[nf] = a1; sA2[nf] = a2;
            nf += fire ? 1 : 0;
            aacc = fire ? a2 : s1;         // FSEL
        }
        s_nf = nf;
        g_n[b] = nf;
    }
    __syncthreads();
    const int nf = s_nf;
    for (int i = threadIdx.x; i < nf; i += blockDim.x) {
        g_Ft[base + i]  = sFt[i];
        g_Fa1[base + i] = sA1[i];
        g_Fa2[base + i] = sA2[i];
    }
}

// ---------------------------------------------------------------------------
// Kernel 5: emit. Block (jb, b) handles 4 output rows. Row j < n:
// sum over t in [F[j-1], F[j]] with weight alpha[t] (interior),
// a2[j-1] at t0 (j>0), a1[j] at t1. Rows >= n: zeros.
// ---------------------------------------------------------------------------
__global__ void k_emit(const float* __restrict__ x, float* __restrict__ out,
                       int B, int S, int D, long long out_size) {
    const int b = blockIdx.y;
    const int tid = threadIdx.x;
    const int n = g_n[b];
    const int base = b * S;
    const int j0 = blockIdx.x * 4;

    for (int jj = 0; jj < 4; jj++) {
        const int j = j0 + jj;
        if (j >= S) break;
        float4* orow = (float4*)(out + ((size_t)b * S + j) * D);
        if (j >= n) {
            orow[tid] = make_float4(0.f, 0.f, 0.f, 0.f);
        } else {
            const int t1 = g_Ft[base + j];
            const int t0 = (j == 0) ? 0 : g_Ft[base + j - 1];
            const float wa1 = g_Fa1[base + j];
            const float wa2 = (j == 0) ? 0.f : g_Fa2[base + j - 1];
            float4 acc = make_float4(0.f, 0.f, 0.f, 0.f);
            for (int t = t0; t <= t1; t++) {
                float wgt = (t == t1) ? wa1
                          : ((j > 0 && t == t0) ? wa2 : g_alpha[base + t]);
                const float4 h = ((const float4*)(x + ((size_t)b * S + t) * D))[tid];
                acc.x += wgt * h.x; acc.y += wgt * h.y;
                acc.z += wgt * h.z; acc.w += wgt * h.w;
            }
            orow[tid] = acc;
        }
    }
    // len_tensor appended after output_c, if space exists
    if (blockIdx.x == 0 && tid == 0 && out_size >= (long long)B * S * D + B)
        out[(size_t)B * S * D + b] = (float)n;
}

// ---------------------------------------------------------------------------
extern "C" void kernel_launch(void* const* d_in, const int* in_sizes, int n_in,
                              void* d_out, int out_size) {
    const float* x      = (const float*)d_in[0];  // (B,S,D)
    const int*   lens   = (const int*)  d_in[1];  // (B,)
    const float* conv_w = (const float*)d_in[2];  // (D,D,3)
    const float* conv_b = (const float*)d_in[3];  // (D,)
    const float* lin_w  = (const float*)d_in[4];  // (1,D)
    const float* lin_b  = (const float*)d_in[5];  // (1,)

    const int B = in_sizes[1];
    const int D = in_sizes[4];
    const int S = in_sizes[0] / (B * D);
    float* out = (float*)d_out;

    // 1) fuse weights (parallel partials + fixed-order combine)
    {
        dim3 g1((D * 3 + 255) / 256, NCHUNK);
        k_fuse_part<<<g1, 256>>>(conv_w, lin_w, D);
        k_fuse_comb<<<(D * 3 + 255) / 256 + 1, 256>>>(conv_b, lin_w, lin_b, D);
    }
    // 2) per-row conv-tap dots (x read once)
    {
        dim3 grid((S + 7) / 8, B);
        k_z<<<grid, 256>>>(x, S, D);
    }
    // 3) alphas
    k_comb<<<(B * S + 255) / 256, 256>>>(lens, B, S);
    // 4) sequential scan per batch
    k_scan<<<B, 256>>>(S);
    // 5) emit output rows + lens
    {
        dim3 grid((S + 3) / 4, B);
        k_emit<<<grid, D / 4>>>(x, out, B, S, D, (long long)out_size);
    }
}